// round 12
// baseline (speedup 1.0000x reference)
#include <cuda_runtime.h>
#include <cuda_fp16.h>
#include <cuda_bf16.h>
#include <cstdint>

#define NN 50000
#define DD 128
#define EE 800000
#define SCAN_BS 1024
#define NB_MAX 64
#define HALF_N 25024   // chunk split (multiple of 64)

// ---------------------------------------------------------------------------
// Scratch (__device__ globals; no allocations allowed)
// ---------------------------------------------------------------------------
__device__ int   g_cnt[NN];
__device__ int   g_rowptr[NN + 1];
__device__ int   g_rank[EE];
__device__ int   g_col[EE];
__device__ float g_dinv[NN];
__device__ __half g_h[(size_t)NN * DD];    // hs = dinv[row] * (X@W)  (fp16)
__device__ float  g_a[(size_t)NN * DD];    // layer-1 output (fp32)

__device__ uint32_t g_wh[2][64 * 128];
__device__ uint32_t g_wl[2][64 * 128];

__device__ volatile int g_flag[NB_MAX];
__device__ int g_aggr[NB_MAX];
__device__ int g_pref[NB_MAX];

// ---------------------------------------------------------------------------
// CSR build
// ---------------------------------------------------------------------------
__global__ void k_zero(int n) {
    int i = blockIdx.x * blockDim.x + threadIdx.x;
    if (i < n) g_cnt[i] = 0;
    if (i < NB_MAX) g_flag[i] = 0;
}

__global__ void k_hist(const int* __restrict__ dst, int e) {
    int i = blockIdx.x * blockDim.x + threadIdx.x;
    int n8 = e >> 3;
    if (i < n8) {
        int4 d0 = __ldg(reinterpret_cast<const int4*>(dst) + 2 * i);
        int4 d1 = __ldg(reinterpret_cast<const int4*>(dst) + 2 * i + 1);
        int dd[8] = {d0.x, d0.y, d0.z, d0.w, d1.x, d1.y, d1.z, d1.w};
        int rr[8];
#pragma unroll
        for (int j = 0; j < 8; j++) rr[j] = atomicAdd(&g_cnt[dd[j]], 1);
        reinterpret_cast<int4*>(g_rank)[2 * i]     = make_int4(rr[0], rr[1], rr[2], rr[3]);
        reinterpret_cast<int4*>(g_rank)[2 * i + 1] = make_int4(rr[4], rr[5], rr[6], rr[7]);
    } else {
        int j = n8 * 8 + (i - n8);
        if (j < e) g_rank[j] = atomicAdd(&g_cnt[dst[j]], 1);
    }
}

__global__ __launch_bounds__(SCAN_BS) void k_scan(int n) {
    __shared__ int s[SCAN_BS];
    __shared__ int s_excl;
    const int b = blockIdx.x;
    const int t = threadIdx.x;
    const int i = b * SCAN_BS + t;

    int c = (i < n) ? g_cnt[i] : 0;
    s[t] = c;
    __syncthreads();
    for (int off = 1; off < SCAN_BS; off <<= 1) {
        int v = (t >= off) ? s[t - off] : 0;
        __syncthreads();
        s[t] += v;
        __syncthreads();
    }
    int incl = s[t];
    int total = s[SCAN_BS - 1];

    if (t == 0) {
        if (b == 0) {
            g_pref[0] = total;
            __threadfence();
            g_flag[0] = 2;
            s_excl = 0;
        } else {
            g_aggr[b] = total;
            __threadfence();
            g_flag[b] = 1;
            int excl = 0;
            for (int j = b - 1; j >= 0; j--) {
                int f;
                do { f = g_flag[j]; } while (f == 0);
                __threadfence();
                if (f == 2) { excl += g_pref[j]; break; }
                excl += g_aggr[j];
            }
            g_pref[b] = excl + total;
            __threadfence();
            g_flag[b] = 2;
            s_excl = excl;
        }
    }
    __syncthreads();
    int ex = s_excl + incl - c;

    if (i < n) {
        g_rowptr[i] = ex;
        g_dinv[i]   = rsqrtf((float)(c + 1));
        if (i == n - 1) g_rowptr[n] = ex + c;
    }
}

__global__ void k_fill(const int* __restrict__ src, const int* __restrict__ dst, int e) {
    int i = blockIdx.x * blockDim.x + threadIdx.x;
    int n8 = e >> 3;
    if (i < n8) {
        int4 s0 = __ldg(reinterpret_cast<const int4*>(src) + 2 * i);
        int4 s1 = __ldg(reinterpret_cast<const int4*>(src) + 2 * i + 1);
        int4 d0 = __ldg(reinterpret_cast<const int4*>(dst) + 2 * i);
        int4 d1 = __ldg(reinterpret_cast<const int4*>(dst) + 2 * i + 1);
        int4 r0 = __ldg(reinterpret_cast<const int4*>(g_rank) + 2 * i);
        int4 r1 = __ldg(reinterpret_cast<const int4*>(g_rank) + 2 * i + 1);
        int ss[8] = {s0.x, s0.y, s0.z, s0.w, s1.x, s1.y, s1.z, s1.w};
        int dd[8] = {d0.x, d0.y, d0.z, d0.w, d1.x, d1.y, d1.z, d1.w};
        int rr[8] = {r0.x, r0.y, r0.z, r0.w, r1.x, r1.y, r1.z, r1.w};
        int pp[8];
#pragma unroll
        for (int j = 0; j < 8; j++) pp[j] = __ldg(&g_rowptr[dd[j]]) + rr[j];
#pragma unroll
        for (int j = 0; j < 8; j++) g_col[pp[j]] = ss[j];
    } else {
        int j = n8 * 8 + (i - n8);
        if (j < e) g_col[__ldg(&g_rowptr[dst[j]]) + g_rank[j]] = src[j];
    }
}

// ---------------------------------------------------------------------------
// Weight split
// ---------------------------------------------------------------------------
__global__ void k_wsplit(const float* __restrict__ W, int which) {
    int i = blockIdx.x * blockDim.x + threadIdx.x;
    if (i >= 64 * 128) return;
    int kk = i >> 7, nn = i & 127;
    float w0 = __ldg(&W[(2 * kk) * 128 + nn]);
    float w1 = __ldg(&W[(2 * kk + 1) * 128 + nn]);
    __nv_bfloat16 h0 = __float2bfloat16(w0);
    __nv_bfloat16 h1 = __float2bfloat16(w1);
    __nv_bfloat16 l0 = __float2bfloat16(w0 - __bfloat162float(h0));
    __nv_bfloat16 l1 = __float2bfloat16(w1 - __bfloat162float(h1));
    __nv_bfloat162 hh = __nv_bfloat162(h0, h1);
    __nv_bfloat162 ll = __nv_bfloat162(l0, l1);
    g_wh[which][i] = *reinterpret_cast<uint32_t*>(&hh);
    g_wl[which][i] = *reinterpret_cast<uint32_t*>(&ll);
}

// ---------------------------------------------------------------------------
// 3x-bf16 mma.sync GEMM over row range [row_base, row_end):
// Yh[row] = fp16( dinv[row] * ((relu?)X[row] @ W) )
// ---------------------------------------------------------------------------
#define LDAB 68

__device__ __forceinline__ void mma_bf16(float* c, const uint32_t* a, const uint32_t* b) {
    asm volatile(
        "mma.sync.aligned.m16n8k16.row.col.f32.bf16.bf16.f32 "
        "{%0,%1,%2,%3}, {%4,%5,%6,%7}, {%8,%9}, {%0,%1,%2,%3};"
        : "+f"(c[0]), "+f"(c[1]), "+f"(c[2]), "+f"(c[3])
        : "r"(a[0]), "r"(a[1]), "r"(a[2]), "r"(a[3]), "r"(b[0]), "r"(b[1]));
}

template <bool RELU>
__global__ __launch_bounds__(256) void k_gemm_mma(const float* __restrict__ X,
                                                  int widx,
                                                  __half* __restrict__ Y,
                                                  int row_base, int row_end) {
    __shared__ uint32_t sAh[64 * LDAB];
    __shared__ uint32_t sAl[64 * LDAB];

    const int tid  = threadIdx.x;
    const int row0 = row_base + blockIdx.x * 64;
    const uint32_t* __restrict__ Bh = g_wh[widx];
    const uint32_t* __restrict__ Bl = g_wl[widx];

#pragma unroll
    for (int idx = tid; idx < 64 * 32; idx += 256) {
        int r  = idx >> 5;
        int c4 = idx & 31;
        int row = row0 + r;
        float4 v = make_float4(0.f, 0.f, 0.f, 0.f);
        if (row < row_end) v = __ldg(reinterpret_cast<const float4*>(X + (size_t)row * DD) + c4);
        if (RELU) {
            v.x = fmaxf(v.x, 0.f); v.y = fmaxf(v.y, 0.f);
            v.z = fmaxf(v.z, 0.f); v.w = fmaxf(v.w, 0.f);
        }
        __nv_bfloat16 hx = __float2bfloat16(v.x), hy = __float2bfloat16(v.y);
        __nv_bfloat16 hz = __float2bfloat16(v.z), hw = __float2bfloat16(v.w);
        __nv_bfloat16 lx = __float2bfloat16(v.x - __bfloat162float(hx));
        __nv_bfloat16 ly = __float2bfloat16(v.y - __bfloat162float(hy));
        __nv_bfloat16 lz = __float2bfloat16(v.z - __bfloat162float(hz));
        __nv_bfloat16 lw = __float2bfloat16(v.w - __bfloat162float(hw));
        __nv_bfloat162 h0 = __nv_bfloat162(hx, hy), h1 = __nv_bfloat162(hz, hw);
        __nv_bfloat162 l0 = __nv_bfloat162(lx, ly), l1 = __nv_bfloat162(lz, lw);
        uint2 hp = make_uint2(*reinterpret_cast<uint32_t*>(&h0), *reinterpret_cast<uint32_t*>(&h1));
        uint2 lp = make_uint2(*reinterpret_cast<uint32_t*>(&l0), *reinterpret_cast<uint32_t*>(&l1));
        *reinterpret_cast<uint2*>(&sAh[r * LDAB + 2 * c4]) = hp;
        *reinterpret_cast<uint2*>(&sAl[r * LDAB + 2 * c4]) = lp;
    }
    __syncthreads();

    const int wid  = tid >> 5;
    const int lane = tid & 31;
    const int gid  = lane >> 2;
    const int tig  = lane & 3;
    const int wm   = wid & 1;
    const int wn   = wid >> 1;

    float acc[2][4][4];
#pragma unroll
    for (int mi = 0; mi < 2; mi++)
#pragma unroll
        for (int ni = 0; ni < 4; ni++)
#pragma unroll
            for (int j = 0; j < 4; j++) acc[mi][ni][j] = 0.f;

#pragma unroll
    for (int ks = 0; ks < 8; ks++) {
        const int kk0 = ks * 8;
        uint32_t ah[2][4], al[2][4];
#pragma unroll
        for (int mi = 0; mi < 2; mi++) {
            int rb = wm * 32 + mi * 16;
            ah[mi][0] = sAh[(rb + gid) * LDAB + kk0 + tig];
            ah[mi][1] = sAh[(rb + gid + 8) * LDAB + kk0 + tig];
            ah[mi][2] = sAh[(rb + gid) * LDAB + kk0 + 4 + tig];
            ah[mi][3] = sAh[(rb + gid + 8) * LDAB + kk0 + 4 + tig];
            al[mi][0] = sAl[(rb + gid) * LDAB + kk0 + tig];
            al[mi][1] = sAl[(rb + gid + 8) * LDAB + kk0 + tig];
            al[mi][2] = sAl[(rb + gid) * LDAB + kk0 + 4 + tig];
            al[mi][3] = sAl[(rb + gid + 8) * LDAB + kk0 + 4 + tig];
        }
        uint32_t bh[4][2], bl[4][2];
#pragma unroll
        for (int ni = 0; ni < 4; ni++) {
            int nb = wn * 32 + ni * 8 + gid;
            bh[ni][0] = __ldg(&Bh[(kk0 + tig) * 128 + nb]);
            bh[ni][1] = __ldg(&Bh[(kk0 + 4 + tig) * 128 + nb]);
            bl[ni][0] = __ldg(&Bl[(kk0 + tig) * 128 + nb]);
            bl[ni][1] = __ldg(&Bl[(kk0 + 4 + tig) * 128 + nb]);
        }
#pragma unroll
        for (int mi = 0; mi < 2; mi++)
#pragma unroll
            for (int ni = 0; ni < 4; ni++) {
                mma_bf16(acc[mi][ni], ah[mi], bh[ni]);
                mma_bf16(acc[mi][ni], ah[mi], bl[ni]);
                mma_bf16(acc[mi][ni], al[mi], bh[ni]);
            }
    }

#pragma unroll
    for (int mi = 0; mi < 2; mi++) {
        int r0 = row0 + wm * 32 + mi * 16 + gid;
        float dA = (r0 < row_end)     ? g_dinv[r0]     : 0.f;
        float dB = (r0 + 8 < row_end) ? g_dinv[r0 + 8] : 0.f;
#pragma unroll
        for (int ni = 0; ni < 4; ni++) {
            int col = wn * 32 + ni * 8 + tig * 2;
            if (r0 < row_end)
                *reinterpret_cast<__half2*>(Y + (size_t)r0 * DD + col) =
                    __float22half2_rn(make_float2(acc[mi][ni][0] * dA, acc[mi][ni][1] * dA));
            if (r0 + 8 < row_end)
                *reinterpret_cast<__half2*>(Y + (size_t)(r0 + 8) * DD + col) =
                    __float22half2_rn(make_float2(acc[mi][ni][2] * dB, acc[mi][ni][3] * dB));
        }
    }
}

// ---------------------------------------------------------------------------
// Gather over node range [node_base, node_end):
// out[i] = dinv[i] * (hs[i] + sum_in hs[src]) + b
// 16 lanes per node, unroll 8 -> 4 -> 1.
// ---------------------------------------------------------------------------
__global__ __launch_bounds__(256) void k_gather(const __half* __restrict__ hs,
                                                const float* __restrict__ bias,
                                                float* __restrict__ out,
                                                int node_base, int node_end) {
    int g    = blockIdx.x * blockDim.x + threadIdx.x;
    int node = node_base + (g >> 4);
    int lane = g & 15;
    if (node >= node_end) return;

    const uint4* H = reinterpret_cast<const uint4*>(hs);
    int beg = g_rowptr[node];
    int end = g_rowptr[node + 1];

    float acc[8];
    {
        uint4 sraw = __ldg(&H[(size_t)node * 16 + lane]);
        const __half2* ph = reinterpret_cast<const __half2*>(&sraw);
#pragma unroll
        for (int q = 0; q < 4; q++) {
            float2 f = __half22float2(ph[q]);
            acc[2 * q]     = f.x;
            acc[2 * q + 1] = f.y;
        }
    }

    int e = beg;
    for (; e + 8 <= end; e += 8) {
        int c[8];
#pragma unroll
        for (int j = 0; j < 8; j++) c[j] = __ldg(&g_col[e + j]);
        uint4 v[8];
#pragma unroll
        for (int j = 0; j < 8; j++) v[j] = __ldg(&H[(size_t)c[j] * 16 + lane]);
#pragma unroll
        for (int j = 0; j < 8; j++) {
            const __half2* pv = reinterpret_cast<const __half2*>(&v[j]);
#pragma unroll
            for (int q = 0; q < 4; q++) {
                float2 f = __half22float2(pv[q]);
                acc[2 * q]     += f.x;
                acc[2 * q + 1] += f.y;
            }
        }
    }
    if (e + 4 <= end) {
        int c[4];
#pragma unroll
        for (int j = 0; j < 4; j++) c[j] = __ldg(&g_col[e + j]);
        uint4 v[4];
#pragma unroll
        for (int j = 0; j < 4; j++) v[j] = __ldg(&H[(size_t)c[j] * 16 + lane]);
#pragma unroll
        for (int j = 0; j < 4; j++) {
            const __half2* pv = reinterpret_cast<const __half2*>(&v[j]);
#pragma unroll
            for (int q = 0; q < 4; q++) {
                float2 f = __half22float2(pv[q]);
                acc[2 * q]     += f.x;
                acc[2 * q + 1] += f.y;
            }
        }
        e += 4;
    }
    for (; e < end; e++) {
        uint4 v = __ldg(&H[(size_t)__ldg(&g_col[e]) * 16 + lane]);
        const __half2* pv = reinterpret_cast<const __half2*>(&v);
#pragma unroll
        for (int q = 0; q < 4; q++) {
            float2 f = __half22float2(pv[q]);
            acc[2 * q]     += f.x;
            acc[2 * q + 1] += f.y;
        }
    }

    float dn = g_dinv[node];
    const float4* B4 = reinterpret_cast<const float4*>(bias);
    float4 b0 = __ldg(&B4[lane * 2]);
    float4 b1 = __ldg(&B4[lane * 2 + 1]);
    float4 o0, o1;
    o0.x = fmaf(acc[0], dn, b0.x); o0.y = fmaf(acc[1], dn, b0.y);
    o0.z = fmaf(acc[2], dn, b0.z); o0.w = fmaf(acc[3], dn, b0.w);
    o1.x = fmaf(acc[4], dn, b1.x); o1.y = fmaf(acc[5], dn, b1.y);
    o1.z = fmaf(acc[6], dn, b1.z); o1.w = fmaf(acc[7], dn, b1.w);
    float4* O = reinterpret_cast<float4*>(out);
    O[(size_t)node * 32 + lane * 2]     = o0;
    O[(size_t)node * 32 + lane * 2 + 1] = o1;
}

// ---------------------------------------------------------------------------
// Stream/event resources
// ---------------------------------------------------------------------------
static cudaStream_t g_s1 = nullptr;
static cudaEvent_t  g_evf = nullptr, g_evs = nullptr, g_evj = nullptr;
static cudaEvent_t  g_ev1 = nullptr, g_ev2 = nullptr;
namespace {
struct StreamInit {
    StreamInit() {
        if (cudaStreamCreateWithFlags(&g_s1, cudaStreamNonBlocking) != cudaSuccess) g_s1 = nullptr;
        if (cudaEventCreateWithFlags(&g_evf, cudaEventDisableTiming) != cudaSuccess) g_evf = nullptr;
        if (cudaEventCreateWithFlags(&g_evs, cudaEventDisableTiming) != cudaSuccess) g_evs = nullptr;
        if (cudaEventCreateWithFlags(&g_evj, cudaEventDisableTiming) != cudaSuccess) g_evj = nullptr;
        if (cudaEventCreateWithFlags(&g_ev1, cudaEventDisableTiming) != cudaSuccess) g_ev1 = nullptr;
        if (cudaEventCreateWithFlags(&g_ev2, cudaEventDisableTiming) != cudaSuccess) g_ev2 = nullptr;
        cudaGetLastError();
    }
} g_stream_init;
}

// ---------------------------------------------------------------------------
// Launch
// ---------------------------------------------------------------------------
extern "C" void kernel_launch(void* const* d_in, const int* in_sizes, int n_in,
                              void* d_out, int out_size) {
    const float* x  = (const float*)d_in[0];
    const int*   ei = (const int*)d_in[1];
    const float* W1 = (const float*)d_in[2];
    const float* b1 = (const float*)d_in[3];
    const float* W2 = (const float*)d_in[4];
    const float* b2 = (const float*)d_in[5];
    float* out = (float*)d_out;

    const int n = in_sizes[0] / DD;   // 50000
    const int e = in_sizes[1] / 2;    // 800000
    const int* src = ei;
    const int* dst = ei + e;

    __half* p_h = nullptr; float* p_a = nullptr;
    cudaGetSymbolAddress((void**)&p_h, g_h);
    cudaGetSymbolAddress((void**)&p_a, g_a);

    const int T = 256;
    const int nb = (n + SCAN_BS - 1) / SCAN_BS;
    const int e8threads = (e >> 3) + 8;
    const int h0 = (n < HALF_N) ? n : HALF_N;

    auto gemm_grid = [](int lo, int hi) { return (hi - lo + 63) / 64; };
    auto gath_grid = [T](int lo, int hi) {
        long long t = (long long)(hi - lo) * 16;
        return (int)((t + T - 1) / T);
    };

    const bool fork = (g_s1 && g_evf && g_evs && g_evj && g_ev1 && g_ev2);
    cudaStream_t sc = fork ? g_s1 : (cudaStream_t)0;

    if (fork) {
        cudaEventRecord(g_evf, 0);
        cudaStreamWaitEvent(g_s1, g_evf, 0);
    }

    // Side stream: CSR chain (scan signaled early — GEMM-1 needs dinv)
    k_zero <<<(n + T - 1) / T, T, 0, sc>>>(n);
    k_hist <<<(e8threads + T - 1) / T, T, 0, sc>>>(dst, e);
    k_scan <<<nb, SCAN_BS, 0, sc>>>(n);
    if (fork) cudaEventRecord(g_evs, sc);
    k_fill <<<(e8threads + T - 1) / T, T, 0, sc>>>(src, dst, e);
    if (fork) cudaEventRecord(g_evj, sc);

    // Main stream: weight splits, then GEMM-1
    k_wsplit<<<(64 * 128 + T - 1) / T, T>>>(W1, 0);
    k_wsplit<<<(64 * 128 + T - 1) / T, T>>>(W2, 1);
    if (fork) cudaStreamWaitEvent(0, g_evs, 0);
    k_gemm_mma<false><<<gemm_grid(0, n), 256>>>(x, 0, p_h, 0, n);
    if (fork) cudaStreamWaitEvent(0, g_evj, 0);

    if (fork) {
        // Pipelined: gather1a -> (gather1b || gemm2a) -> gemm2b -> gather2
        k_gather<<<gath_grid(0, h0), T>>>(p_h, b1, p_a, 0, h0);
        cudaEventRecord(g_ev1, 0);
        k_gather<<<gath_grid(h0, n), T>>>(p_h, b1, p_a, h0, n);

        cudaStreamWaitEvent(g_s1, g_ev1, 0);
        k_gemm_mma<true><<<gemm_grid(0, h0), 256, 0, g_s1>>>(p_a, 1, p_h, 0, h0);
        cudaEventRecord(g_ev2, g_s1);

        k_gemm_mma<true><<<gemm_grid(h0, n), 256>>>(p_a, 1, p_h, h0, n);
        cudaStreamWaitEvent(0, g_ev2, 0);
        k_gather<<<gath_grid(0, n), T>>>(p_h, b2, out, 0, n);
    } else {
        k_gather<<<gath_grid(0, n), T>>>(p_h, b1, p_a, 0, n);
        k_gemm_mma<true><<<gemm_grid(0, n), 256>>>(p_a, 1, p_h, 0, n);
        k_gather<<<gath_grid(0, n), T>>>(p_h, b2, out, 0, n);
    }
}

// round 14
// speedup vs baseline: 1.0210x; 1.0210x over previous
#include <cuda_runtime.h>
#include <cuda_fp16.h>
#include <cuda_bf16.h>
#include <cstdint>

#define NN 50000
#define DD 128
#define EE 800000
#define SCAN_BS 1024
#define NB_MAX 64

// ---------------------------------------------------------------------------
// Scratch (__device__ globals; zero-initialized at load, re-zeroed at end of
// each launch so every call sees identical state — no allocations allowed)
// ---------------------------------------------------------------------------
__device__ int   g_cnt[NN];
__device__ int   g_rowptr[NN + 1];
__device__ int   g_rank[EE];
__device__ int   g_col[EE];
__device__ float g_dinv[NN];
__device__ __half g_h[(size_t)NN * DD];    // layer-1 hs = dinv*(X@W1)   (fp16)
__device__ __half g_h2[(size_t)NN * DD];   // layer-2 hs = dinv*(x@W2)   (fp16)

__device__ uint32_t g_wh[2][64 * 128];
__device__ uint32_t g_wl[2][64 * 128];

__device__ volatile int g_flag[NB_MAX];
__device__ int g_aggr[NB_MAX];
__device__ int g_pref[NB_MAX];

// ---------------------------------------------------------------------------
// CSR build
// ---------------------------------------------------------------------------
__global__ void k_hist(const int* __restrict__ dst, int e) {
    int i = blockIdx.x * blockDim.x + threadIdx.x;
    int n8 = e >> 3;
    if (i < n8) {
        int4 d0 = __ldg(reinterpret_cast<const int4*>(dst) + 2 * i);
        int4 d1 = __ldg(reinterpret_cast<const int4*>(dst) + 2 * i + 1);
        int dd[8] = {d0.x, d0.y, d0.z, d0.w, d1.x, d1.y, d1.z, d1.w};
        int rr[8];
#pragma unroll
        for (int j = 0; j < 8; j++) rr[j] = atomicAdd(&g_cnt[dd[j]], 1);
        reinterpret_cast<int4*>(g_rank)[2 * i]     = make_int4(rr[0], rr[1], rr[2], rr[3]);
        reinterpret_cast<int4*>(g_rank)[2 * i + 1] = make_int4(rr[4], rr[5], rr[6], rr[7]);
    } else {
        int j = n8 * 8 + (i - n8);
        if (j < e) g_rank[j] = atomicAdd(&g_cnt[dst[j]], 1);
    }
}

__global__ __launch_bounds__(SCAN_BS) void k_scan(int n) {
    __shared__ int s[SCAN_BS];
    __shared__ int s_excl;
    const int b = blockIdx.x;
    const int t = threadIdx.x;
    const int i = b * SCAN_BS + t;

    int c = (i < n) ? g_cnt[i] : 0;
    s[t] = c;
    __syncthreads();
    for (int off = 1; off < SCAN_BS; off <<= 1) {
        int v = (t >= off) ? s[t - off] : 0;
        __syncthreads();
        s[t] += v;
        __syncthreads();
    }
    int incl = s[t];
    int total = s[SCAN_BS - 1];

    if (t == 0) {
        if (b == 0) {
            g_pref[0] = total;
            __threadfence();
            g_flag[0] = 2;
            s_excl = 0;
        } else {
            g_aggr[b] = total;
            __threadfence();
            g_flag[b] = 1;
            int excl = 0;
            for (int j = b - 1; j >= 0; j--) {
                int f;
                do { f = g_flag[j]; } while (f == 0);
                __threadfence();
                if (f == 2) { excl += g_pref[j]; break; }
                excl += g_aggr[j];
            }
            g_pref[b] = excl + total;
            __threadfence();
            g_flag[b] = 2;
            s_excl = excl;
        }
    }
    __syncthreads();
    int ex = s_excl + incl - c;

    if (i < n) {
        g_rowptr[i] = ex;
        g_dinv[i]   = rsqrtf((float)(c + 1));
        if (i == n - 1) g_rowptr[n] = ex + c;
    }
}

__global__ void k_fill(const int* __restrict__ src, const int* __restrict__ dst, int e) {
    int i = blockIdx.x * blockDim.x + threadIdx.x;
    int n8 = e >> 3;
    if (i < n8) {
        int4 s0 = __ldg(reinterpret_cast<const int4*>(src) + 2 * i);
        int4 s1 = __ldg(reinterpret_cast<const int4*>(src) + 2 * i + 1);
        int4 d0 = __ldg(reinterpret_cast<const int4*>(dst) + 2 * i);
        int4 d1 = __ldg(reinterpret_cast<const int4*>(dst) + 2 * i + 1);
        int4 r0 = __ldg(reinterpret_cast<const int4*>(g_rank) + 2 * i);
        int4 r1 = __ldg(reinterpret_cast<const int4*>(g_rank) + 2 * i + 1);
        int ss[8] = {s0.x, s0.y, s0.z, s0.w, s1.x, s1.y, s1.z, s1.w};
        int dd[8] = {d0.x, d0.y, d0.z, d0.w, d1.x, d1.y, d1.z, d1.w};
        int rr[8] = {r0.x, r0.y, r0.z, r0.w, r1.x, r1.y, r1.z, r1.w};
        int pp[8];
#pragma unroll
        for (int j = 0; j < 8; j++) pp[j] = __ldg(&g_rowptr[dd[j]]) + rr[j];
#pragma unroll
        for (int j = 0; j < 8; j++) g_col[pp[j]] = ss[j];
    } else {
        int j = n8 * 8 + (i - n8);
        if (j < e) g_col[__ldg(&g_rowptr[dst[j]]) + g_rank[j]] = src[j];
    }
}

// reset scratch for the next invocation (runs last)
__global__ void k_zero(int n) {
    int i = blockIdx.x * blockDim.x + threadIdx.x;
    if (i < n) g_cnt[i] = 0;
    if (i < NB_MAX) g_flag[i] = 0;
}

// ---------------------------------------------------------------------------
// Weight split (both layers in one kernel)
// ---------------------------------------------------------------------------
__global__ void k_wsplit2(const float* __restrict__ W1, const float* __restrict__ W2) {
    int g = blockIdx.x * blockDim.x + threadIdx.x;
    if (g >= 2 * 64 * 128) return;
    int which = g >> 13;
    int i = g & 8191;
    const float* W = which ? W2 : W1;
    int kk = i >> 7, nn = i & 127;
    float w0 = __ldg(&W[(2 * kk) * 128 + nn]);
    float w1 = __ldg(&W[(2 * kk + 1) * 128 + nn]);
    __nv_bfloat16 h0 = __float2bfloat16(w0);
    __nv_bfloat16 h1 = __float2bfloat16(w1);
    __nv_bfloat16 l0 = __float2bfloat16(w0 - __bfloat162float(h0));
    __nv_bfloat16 l1 = __float2bfloat16(w1 - __bfloat162float(h1));
    __nv_bfloat162 hh = __nv_bfloat162(h0, h1);
    __nv_bfloat162 ll = __nv_bfloat162(l0, l1);
    g_wh[which][i] = *reinterpret_cast<uint32_t*>(&hh);
    g_wl[which][i] = *reinterpret_cast<uint32_t*>(&ll);
}

// ---------------------------------------------------------------------------
// Shared MMA machinery
// ---------------------------------------------------------------------------
#define LDAB 68

__device__ __forceinline__ void mma_bf16(float* c, const uint32_t* a, const uint32_t* b) {
    asm volatile(
        "mma.sync.aligned.m16n8k16.row.col.f32.bf16.bf16.f32 "
        "{%0,%1,%2,%3}, {%4,%5,%6,%7}, {%8,%9}, {%0,%1,%2,%3};"
        : "+f"(c[0]), "+f"(c[1]), "+f"(c[2]), "+f"(c[3])
        : "r"(a[0]), "r"(a[1]), "r"(a[2]), "r"(a[3]), "r"(b[0]), "r"(b[1]));
}

__device__ __forceinline__ void gemm_tile_body(const uint32_t* sAh, const uint32_t* sAl,
                                               int widx, __half* __restrict__ Y,
                                               int row0, int row_end, int tid) {
    const uint32_t* __restrict__ Bh = g_wh[widx];
    const uint32_t* __restrict__ Bl = g_wl[widx];
    const int wid  = tid >> 5;
    const int lane = tid & 31;
    const int gid  = lane >> 2;
    const int tig  = lane & 3;
    const int wm   = wid & 1;
    const int wn   = wid >> 1;

    float acc[2][4][4];
#pragma unroll
    for (int mi = 0; mi < 2; mi++)
#pragma unroll
        for (int ni = 0; ni < 4; ni++)
#pragma unroll
            for (int j = 0; j < 4; j++) acc[mi][ni][j] = 0.f;

#pragma unroll
    for (int ks = 0; ks < 8; ks++) {
        const int kk0 = ks * 8;
        uint32_t ah[2][4], al[2][4];
#pragma unroll
        for (int mi = 0; mi < 2; mi++) {
            int rb = wm * 32 + mi * 16;
            ah[mi][0] = sAh[(rb + gid) * LDAB + kk0 + tig];
            ah[mi][1] = sAh[(rb + gid + 8) * LDAB + kk0 + tig];
            ah[mi][2] = sAh[(rb + gid) * LDAB + kk0 + 4 + tig];
            ah[mi][3] = sAh[(rb + gid + 8) * LDAB + kk0 + 4 + tig];
            al[mi][0] = sAl[(rb + gid) * LDAB + kk0 + tig];
            al[mi][1] = sAl[(rb + gid + 8) * LDAB + kk0 + tig];
            al[mi][2] = sAl[(rb + gid) * LDAB + kk0 + 4 + tig];
            al[mi][3] = sAl[(rb + gid + 8) * LDAB + kk0 + 4 + tig];
        }
        uint32_t bh[4][2], bl[4][2];
#pragma unroll
        for (int ni = 0; ni < 4; ni++) {
            int nb = wn * 32 + ni * 8 + gid;
            bh[ni][0] = __ldg(&Bh[(kk0 + tig) * 128 + nb]);
            bh[ni][1] = __ldg(&Bh[(kk0 + 4 + tig) * 128 + nb]);
            bl[ni][0] = __ldg(&Bl[(kk0 + tig) * 128 + nb]);
            bl[ni][1] = __ldg(&Bl[(kk0 + 4 + tig) * 128 + nb]);
        }
#pragma unroll
        for (int mi = 0; mi < 2; mi++)
#pragma unroll
            for (int ni = 0; ni < 4; ni++) {
                mma_bf16(acc[mi][ni], ah[mi], bh[ni]);
                mma_bf16(acc[mi][ni], ah[mi], bl[ni]);
                mma_bf16(acc[mi][ni], al[mi], bh[ni]);
            }
    }

#pragma unroll
    for (int mi = 0; mi < 2; mi++) {
        int r0 = row0 + wm * 32 + mi * 16 + gid;
        float dA = (r0 < row_end)     ? g_dinv[r0]     : 0.f;
        float dB = (r0 + 8 < row_end) ? g_dinv[r0 + 8] : 0.f;
#pragma unroll
        for (int ni = 0; ni < 4; ni++) {
            int col = wn * 32 + ni * 8 + tig * 2;
            if (r0 < row_end)
                *reinterpret_cast<__half2*>(Y + (size_t)r0 * DD + col) =
                    __float22half2_rn(make_float2(acc[mi][ni][0] * dA, acc[mi][ni][1] * dA));
            if (r0 + 8 < row_end)
                *reinterpret_cast<__half2*>(Y + (size_t)(r0 + 8) * DD + col) =
                    __float22half2_rn(make_float2(acc[mi][ni][2] * dB, acc[mi][ni][3] * dB));
        }
    }
}

__device__ __forceinline__ void split2(float a, float b, uint32_t& hp, uint32_t& lp) {
    __nv_bfloat16 ha = __float2bfloat16(a), hb = __float2bfloat16(b);
    __nv_bfloat16 la = __float2bfloat16(a - __bfloat162float(ha));
    __nv_bfloat16 lb = __float2bfloat16(b - __bfloat162float(hb));
    __nv_bfloat162 h = __nv_bfloat162(ha, hb);
    __nv_bfloat162 l = __nv_bfloat162(la, lb);
    hp = *reinterpret_cast<uint32_t*>(&h);
    lp = *reinterpret_cast<uint32_t*>(&l);
}

// ---------------------------------------------------------------------------
// GEMM-1: g_h[row] = fp16( dinv[row] * (X[row] @ W1) )
// ---------------------------------------------------------------------------
__global__ __launch_bounds__(256) void k_gemm1(const float* __restrict__ X,
                                               __half* __restrict__ Y, int n) {
    __shared__ uint32_t sAh[64 * LDAB];
    __shared__ uint32_t sAl[64 * LDAB];
    const int tid  = threadIdx.x;
    const int row0 = blockIdx.x * 64;

#pragma unroll
    for (int idx = tid; idx < 64 * 32; idx += 256) {
        int r  = idx >> 5;
        int c4 = idx & 31;
        int row = row0 + r;
        float4 v = make_float4(0.f, 0.f, 0.f, 0.f);
        if (row < n) v = __ldg(reinterpret_cast<const float4*>(X + (size_t)row * DD) + c4);
        uint32_t h0, l0, h1, l1;
        split2(v.x, v.y, h0, l0);
        split2(v.z, v.w, h1, l1);
        *reinterpret_cast<uint2*>(&sAh[r * LDAB + 2 * c4]) = make_uint2(h0, h1);
        *reinterpret_cast<uint2*>(&sAl[r * LDAB + 2 * c4]) = make_uint2(l0, l1);
    }
    __syncthreads();
    gemm_tile_body(sAh, sAl, 0, Y, row0, n, tid);
}

// ---------------------------------------------------------------------------
// FUSED layer-2: per 64-row tile, gather + bias + relu -> A tile -> GEMM.
// Reads g_h (all nodes), writes g_h2 (own tile) — distinct buffers, no race.
// 256 threads = 16 lanes x 16 slots; each slot handles 4 nodes sequentially.
// ---------------------------------------------------------------------------
__global__ __launch_bounds__(256) void k_agg_gemm(const __half* __restrict__ hs,
                                                  const float* __restrict__ bias,
                                                  __half* __restrict__ Y, int n) {
    __shared__ uint32_t sAh[64 * LDAB];
    __shared__ uint32_t sAl[64 * LDAB];
    const int tid  = threadIdx.x;
    const int lane = tid & 15;
    const int slot = tid >> 4;
    const int row0 = blockIdx.x * 64;

    const uint4* H = reinterpret_cast<const uint4*>(hs);
    const float4* B4 = reinterpret_cast<const float4*>(bias);
    float4 bb0 = __ldg(&B4[lane * 2]);
    float4 bb1 = __ldg(&B4[lane * 2 + 1]);

#pragma unroll
    for (int k = 0; k < 4; k++) {
        int r = slot * 4 + k;
        int node = row0 + r;
        uint32_t* dh = &sAh[r * LDAB + lane * 4];
        uint32_t* dl = &sAl[r * LDAB + lane * 4];

        if (node < n) {
            float acc[8];
            {
                uint4 sraw = __ldg(&H[(size_t)node * 16 + lane]);
                const __half2* ph = reinterpret_cast<const __half2*>(&sraw);
#pragma unroll
                for (int q = 0; q < 4; q++) {
                    float2 f = __half22float2(ph[q]);
                    acc[2 * q]     = f.x;
                    acc[2 * q + 1] = f.y;
                }
            }
            int e   = g_rowptr[node];
            int end = g_rowptr[node + 1];
            for (; e + 8 <= end; e += 8) {
                int c[8];
#pragma unroll
                for (int j = 0; j < 8; j++) c[j] = __ldg(&g_col[e + j]);
                uint4 v[8];
#pragma unroll
                for (int j = 0; j < 8; j++) v[j] = __ldg(&H[(size_t)c[j] * 16 + lane]);
#pragma unroll
                for (int j = 0; j < 8; j++) {
                    const __half2* pv = reinterpret_cast<const __half2*>(&v[j]);
#pragma unroll
                    for (int q = 0; q < 4; q++) {
                        float2 f = __half22float2(pv[q]);
                        acc[2 * q]     += f.x;
                        acc[2 * q + 1] += f.y;
                    }
                }
            }
            if (e + 4 <= end) {
                int c[4];
#pragma unroll
                for (int j = 0; j < 4; j++) c[j] = __ldg(&g_col[e + j]);
                uint4 v[4];
#pragma unroll
                for (int j = 0; j < 4; j++) v[j] = __ldg(&H[(size_t)c[j] * 16 + lane]);
#pragma unroll
                for (int j = 0; j < 4; j++) {
                    const __half2* pv = reinterpret_cast<const __half2*>(&v[j]);
#pragma unroll
                    for (int q = 0; q < 4; q++) {
                        float2 f = __half22float2(pv[q]);
                        acc[2 * q]     += f.x;
                        acc[2 * q + 1] += f.y;
                    }
                }
                e += 4;
            }
            for (; e < end; e++) {
                uint4 v = __ldg(&H[(size_t)__ldg(&g_col[e]) * 16 + lane]);
                const __half2* pv = reinterpret_cast<const __half2*>(&v);
#pragma unroll
                for (int q = 0; q < 4; q++) {
                    float2 f = __half22float2(pv[q]);
                    acc[2 * q]     += f.x;
                    acc[2 * q + 1] += f.y;
                }
            }

            float dn = g_dinv[node];
            float xo[8];
            xo[0] = fmaxf(fmaf(acc[0], dn, bb0.x), 0.f);
            xo[1] = fmaxf(fmaf(acc[1], dn, bb0.y), 0.f);
            xo[2] = fmaxf(fmaf(acc[2], dn, bb0.z), 0.f);
            xo[3] = fmaxf(fmaf(acc[3], dn, bb0.w), 0.f);
            xo[4] = fmaxf(fmaf(acc[4], dn, bb1.x), 0.f);
            xo[5] = fmaxf(fmaf(acc[5], dn, bb1.y), 0.f);
            xo[6] = fmaxf(fmaf(acc[6], dn, bb1.z), 0.f);
            xo[7] = fmaxf(fmaf(acc[7], dn, bb1.w), 0.f);

            uint32_t hp[4], lp[4];
            split2(xo[0], xo[1], hp[0], lp[0]);
            split2(xo[2], xo[3], hp[1], lp[1]);
            split2(xo[4], xo[5], hp[2], lp[2]);
            split2(xo[6], xo[7], hp[3], lp[3]);
            *reinterpret_cast<uint4*>(dh) = make_uint4(hp[0], hp[1], hp[2], hp[3]);
            *reinterpret_cast<uint4*>(dl) = make_uint4(lp[0], lp[1], lp[2], lp[3]);
        } else {
            *reinterpret_cast<uint4*>(dh) = make_uint4(0, 0, 0, 0);
            *reinterpret_cast<uint4*>(dl) = make_uint4(0, 0, 0, 0);
        }
    }
    __syncthreads();
    gemm_tile_body(sAh, sAl, 1, Y, row0, n, tid);
}

// ---------------------------------------------------------------------------
// Final gather: out[i] = dinv[i] * (hs2[i] + sum_in hs2[src]) + b2  (fp32 out)
// ---------------------------------------------------------------------------
__global__ __launch_bounds__(256) void k_gather(const __half* __restrict__ hs,
                                                const float* __restrict__ bias,
                                                float* __restrict__ out, int n) {
    int g    = blockIdx.x * blockDim.x + threadIdx.x;
    int node = g >> 4;
    int lane = g & 15;
    if (node >= n) return;

    const uint4* H = reinterpret_cast<const uint4*>(hs);
    int e   = g_rowptr[node];
    int end = g_rowptr[node + 1];

    float acc[8];
    {
        uint4 sraw = __ldg(&H[(size_t)node * 16 + lane]);
        const __half2* ph = reinterpret_cast<const __half2*>(&sraw);
#pragma unroll
        for (int q = 0; q < 4; q++) {
            float2 f = __half22float2(ph[q]);
            acc[2 * q]     = f.x;
            acc[2 * q + 1] = f.y;
        }
    }

    for (; e + 8 <= end; e += 8) {
        int c[8];
#pragma unroll
        for (int j = 0; j < 8; j++) c[j] = __ldg(&g_col[e + j]);
        uint4 v[8];
#pragma unroll
        for (int j = 0; j < 8; j++) v[j] = __ldg(&H[(size_t)c[j] * 16 + lane]);
#pragma unroll
        for (int j = 0; j < 8; j++) {
            const __half2* pv = reinterpret_cast<const __half2*>(&v[j]);
#pragma unroll
            for (int q = 0; q < 4; q++) {
                float2 f = __half22float2(pv[q]);
                acc[2 * q]     += f.x;
                acc[2 * q + 1] += f.y;
            }
        }
    }
    if (e + 4 <= end) {
        int c[4];
#pragma unroll
        for (int j = 0; j < 4; j++) c[j] = __ldg(&g_col[e + j]);
        uint4 v[4];
#pragma unroll
        for (int j = 0; j < 4; j++) v[j] = __ldg(&H[(size_t)c[j] * 16 + lane]);
#pragma unroll
        for (int j = 0; j < 4; j++) {
            const __half2* pv = reinterpret_cast<const __half2*>(&v[j]);
#pragma unroll
            for (int q = 0; q < 4; q++) {
                float2 f = __half22float2(pv[q]);
                acc[2 * q]     += f.x;
                acc[2 * q + 1] += f.y;
            }
        }
        e += 4;
    }
    for (; e < end; e++) {
        uint4 v = __ldg(&H[(size_t)__ldg(&g_col[e]) * 16 + lane]);
        const __half2* pv = reinterpret_cast<const __half2*>(&v);
#pragma unroll
        for (int q = 0; q < 4; q++) {
            float2 f = __half22float2(pv[q]);
            acc[2 * q]     += f.x;
            acc[2 * q + 1] += f.y;
        }
    }

    float dn = g_dinv[node];
    const float4* B4 = reinterpret_cast<const float4*>(bias);
    float4 b0 = __ldg(&B4[lane * 2]);
    float4 b1 = __ldg(&B4[lane * 2 + 1]);
    float4 o0, o1;
    o0.x = fmaf(acc[0], dn, b0.x); o0.y = fmaf(acc[1], dn, b0.y);
    o0.z = fmaf(acc[2], dn, b0.z); o0.w = fmaf(acc[3], dn, b0.w);
    o1.x = fmaf(acc[4], dn, b1.x); o1.y = fmaf(acc[5], dn, b1.y);
    o1.z = fmaf(acc[6], dn, b1.z); o1.w = fmaf(acc[7], dn, b1.w);
    float4* O = reinterpret_cast<float4*>(out);
    O[(size_t)node * 32 + lane * 2]     = o0;
    O[(size_t)node * 32 + lane * 2 + 1] = o1;
}

// ---------------------------------------------------------------------------
// Stream/event resources
// ---------------------------------------------------------------------------
static cudaStream_t g_s1 = nullptr;
static cudaEvent_t  g_evf = nullptr, g_evs = nullptr, g_evj = nullptr;
namespace {
struct StreamInit {
    StreamInit() {
        if (cudaStreamCreateWithFlags(&g_s1, cudaStreamNonBlocking) != cudaSuccess) g_s1 = nullptr;
        if (cudaEventCreateWithFlags(&g_evf, cudaEventDisableTiming) != cudaSuccess) g_evf = nullptr;
        if (cudaEventCreateWithFlags(&g_evs, cudaEventDisableTiming) != cudaSuccess) g_evs = nullptr;
        if (cudaEventCreateWithFlags(&g_evj, cudaEventDisableTiming) != cudaSuccess) g_evj = nullptr;
        cudaGetLastError();
    }
} g_stream_init;
}

// ---------------------------------------------------------------------------
// Launch
// ---------------------------------------------------------------------------
extern "C" void kernel_launch(void* const* d_in, const int* in_sizes, int n_in,
                              void* d_out, int out_size) {
    const float* x  = (const float*)d_in[0];
    const int*   ei = (const int*)d_in[1];
    const float* W1 = (const float*)d_in[2];
    const float* b1 = (const float*)d_in[3];
    const float* W2 = (const float*)d_in[4];
    const float* b2 = (const float*)d_in[5];
    float* out = (float*)d_out;

    const int n = in_sizes[0] / DD;   // 50000
    const int e = in_sizes[1] / 2;    // 800000
    const int* src = ei;
    const int* dst = ei + e;

    __half *p_h = nullptr, *p_h2 = nullptr;
    cudaGetSymbolAddress((void**)&p_h,  g_h);
    cudaGetSymbolAddress((void**)&p_h2, g_h2);

    const int T = 256;
    const int nb = (n + SCAN_BS - 1) / SCAN_BS;
    const int e8threads = (e >> 3) + 8;
    const int gemm_blocks = (n + 63) / 64;
    const long long ngt = (long long)n * 16;
    const int gath_blocks = (int)((ngt + T - 1) / T);

    const bool fork = (g_s1 && g_evf && g_evs && g_evj);
    cudaStream_t sc = fork ? g_s1 : (cudaStream_t)0;

    if (fork) {
        cudaEventRecord(g_evf, 0);
        cudaStreamWaitEvent(g_s1, g_evf, 0);
    }

    // Side stream: CSR chain (cnt/flag pre-zeroed by previous call's k_zero,
    // or static-init zeros on the first run).
    k_hist <<<(e8threads + T - 1) / T, T, 0, sc>>>(dst, e);
    k_scan <<<nb, SCAN_BS, 0, sc>>>(n);
    if (fork) cudaEventRecord(g_evs, sc);
    k_fill <<<(e8threads + T - 1) / T, T, 0, sc>>>(src, dst, e);
    if (fork) cudaEventRecord(g_evj, sc);

    // Main stream
    k_wsplit2<<<(2 * 64 * 128 + T - 1) / T, T>>>(W1, W2);
    if (fork) cudaStreamWaitEvent(0, g_evs, 0);          // gemm1 needs dinv
    k_gemm1<<<gemm_blocks, 256>>>(x, p_h, n);
    if (fork) cudaStreamWaitEvent(0, g_evj, 0);          // fused needs g_col
    k_agg_gemm<<<gemm_blocks, 256>>>(p_h, b1, p_h2, n);  // gather1 + GEMM-2
    k_gather<<<gath_blocks, T>>>(p_h2, b2, out, n);

    // reset scratch for next invocation
    k_zero<<<(n + T - 1) / T, T>>>(n);
}